// round 6
// baseline (speedup 1.0000x reference)
#include <cuda_runtime.h>

// Problem constants
#define NCH   8192      // channels
#define NTT   4096      // time samples
#define NLAGS 103       // output lags (-51..51)
#define LPADL 112       // padded lag count (7 warps x 16 lags)
#define RAWS  112       // raw scratch row stride
#define APAD  4208      // padded data1 row: 51 zeros + 4096 + tail zeros (>= 4095+111+1)
#define XCOR_N (NCH * NLAGS)

// Scratch for raw (pre-moving-average) cross-correlation: 8192 x 112 floats (~3.67 MB)
__device__ float g_raw[(size_t)NCH * RAWS];

// ---------------------------------------------------------------------------
// Stage 1: per-channel cross-correlation.
//   R[c][l] = sum_t data1[c][t + l - 51] * data2[c][t],  l in [0,103)
// One block per channel. 224 threads = 7 warps; warp w owns lags [16w, 16w+16).
// Lanes split t; per iter each lane handles 4 consecutive t with a 20-float
// register window of a (conflict-free contiguous LDS.128 across the warp).
// ---------------------------------------------------------------------------
__global__ __launch_bounds__(224, 4)
void xcorr_stage1(const float* __restrict__ d1, const float* __restrict__ d2)
{
    __shared__ __align__(16) float a_sm[APAD];
    __shared__ __align__(16) float b_sm[NTT];

    const int c   = blockIdx.x;
    const int tid = threadIdx.x;

    const float* __restrict__ r1 = d1 + (size_t)c * NTT;
    const float* __restrict__ r2 = d2 + (size_t)c * NTT;

    // Zero the pad regions of a_sm: [0,51) and [51+NTT, APAD)
    for (int i = tid; i < 51; i += 224) a_sm[i] = 0.0f;
    for (int i = 51 + NTT + tid; i < APAD; i += 224) a_sm[i] = 0.0f;

    // Bulk fill: vectorized global loads, scalar stores for the 51-offset a.
    for (int k = tid; k < NTT / 4; k += 224) {
        float4 v1 = reinterpret_cast<const float4*>(r1)[k];
        a_sm[51 + 4 * k + 0] = v1.x;
        a_sm[51 + 4 * k + 1] = v1.y;
        a_sm[51 + 4 * k + 2] = v1.z;
        a_sm[51 + 4 * k + 3] = v1.w;
        reinterpret_cast<float4*>(b_sm)[k] = reinterpret_cast<const float4*>(r2)[k];
    }
    __syncthreads();

    const int warp = tid >> 5;          // 0..6  -> lag group
    const int lane = tid & 31;
    const int lb   = warp * 16;         // lag base (multiple of 16 -> 64B aligned)

    float acc[16];
#pragma unroll
    for (int j = 0; j < 16; ++j) acc[j] = 0.0f;

    const float* __restrict__ ap = a_sm + lb;

#pragma unroll 2
    for (int iter = 0; iter < 32; ++iter) {
        const int t0 = iter * 128 + lane * 4;   // lanes cover 128 contiguous t

        const float4 b4 = *reinterpret_cast<const float4*>(b_sm + t0);
        const float4 w0 = *reinterpret_cast<const float4*>(ap + t0);
        const float4 w1 = *reinterpret_cast<const float4*>(ap + t0 + 4);
        const float4 w2 = *reinterpret_cast<const float4*>(ap + t0 + 8);
        const float4 w3 = *reinterpret_cast<const float4*>(ap + t0 + 12);
        const float4 w4 = *reinterpret_cast<const float4*>(ap + t0 + 16);

        float aw[20];
        aw[0]  = w0.x; aw[1]  = w0.y; aw[2]  = w0.z; aw[3]  = w0.w;
        aw[4]  = w1.x; aw[5]  = w1.y; aw[6]  = w1.z; aw[7]  = w1.w;
        aw[8]  = w2.x; aw[9]  = w2.y; aw[10] = w2.z; aw[11] = w2.w;
        aw[12] = w3.x; aw[13] = w3.y; aw[14] = w3.z; aw[15] = w3.w;
        aw[16] = w4.x; aw[17] = w4.y; aw[18] = w4.z; aw[19] = w4.w;

        float bv[4];
        bv[0] = b4.x; bv[1] = b4.y; bv[2] = b4.z; bv[3] = b4.w;

#pragma unroll
        for (int k = 0; k < 4; ++k) {
#pragma unroll
            for (int j = 0; j < 16; ++j) {
                acc[j] = fmaf(aw[j + k], bv[k], acc[j]);
            }
        }
    }

    // Warp-level reduce over lanes (lanes split t, warp owns the 16 lags).
#pragma unroll
    for (int j = 0; j < 16; ++j) {
#pragma unroll
        for (int o = 16; o > 0; o >>= 1) {
            acc[j] += __shfl_xor_sync(0xffffffffu, acc[j], o);
        }
    }

    if (lane == 0) {
        float* dst = g_raw + (size_t)c * RAWS + lb;
#pragma unroll
        for (int j = 0; j < 16; ++j) dst[j] = acc[j];
    }
}

// ---------------------------------------------------------------------------
// Stage 2: moving average over CHANNELS (window 20: channels [c-10, c+9],
// zero-padded), write xcor, then per-channel argmax|R| / max / min / tmax.
// One block per output channel. Scratch rows are L2-resident.
// ---------------------------------------------------------------------------
__global__ __launch_bounds__(128)
void xcorr_stage2(float* __restrict__ out)
{
    const int c   = blockIdx.x;
    const int tid = threadIdx.x;

    __shared__ float sh[NLAGS];

    if (tid < NLAGS) {
        int k0 = c - 10; if (k0 < 0) k0 = 0;
        int k1 = c + 9;  if (k1 > NCH - 1) k1 = NCH - 1;
        float s = 0.0f;
        for (int k = k0; k <= k1; ++k) {
            s += g_raw[(size_t)k * RAWS + tid];
        }
        s *= (1.0f / 20.0f);
        out[(size_t)c * NLAGS + tid] = s;
        sh[tid] = s;
    }
    __syncthreads();

    if (tid < 32) {
        float bestAbs = -1.0f;
        int   bestIdx = 0;
        float bestVal = 0.0f;
        float vpos = -3.402823466e38f;
        float vneg =  3.402823466e38f;

        for (int l = tid; l < NLAGS; l += 32) {
            float v  = sh[l];
            float av = fabsf(v);
            if (av > bestAbs) { bestAbs = av; bestIdx = l; bestVal = v; }
            vpos = fmaxf(vpos, v);
            vneg = fminf(vneg, v);
        }
#pragma unroll
        for (int o = 16; o > 0; o >>= 1) {
            float oa = __shfl_down_sync(0xffffffffu, bestAbs, o);
            int   oi = __shfl_down_sync(0xffffffffu, bestIdx, o);
            float ov = __shfl_down_sync(0xffffffffu, bestVal, o);
            if (oa > bestAbs || (oa == bestAbs && oi < bestIdx)) {
                bestAbs = oa; bestIdx = oi; bestVal = ov;
            }
            vpos = fmaxf(vpos, __shfl_down_sync(0xffffffffu, vpos, o));
            vneg = fminf(vneg, __shfl_down_sync(0xffffffffu, vneg, o));
        }

        if (tid == 0) {
            const float vside = (bestVal >= 0.0f) ? vneg : vpos;
            out[(size_t)XCOR_N + c]            = bestVal;                       // vmax (vmain)
            out[(size_t)XCOR_N + NCH + c]      = vside;                         // vmin (vside)
            out[(size_t)XCOR_N + 2 * NCH + c]  = (float)(bestIdx - 51) * 0.01f; // tmax
        }
    }
}

// ---------------------------------------------------------------------------
// kernel_launch: inputs per metadata order: data1 (f32, NC*NT), data2 (f32,
// NC*NT), event1 (i32,1), event2 (i32,1) — events are unused by the reference.
// ---------------------------------------------------------------------------
extern "C" void kernel_launch(void* const* d_in, const int* in_sizes, int n_in,
                              void* d_out, int out_size)
{
    const float* data1 = (const float*)d_in[0];
    const float* data2 = (const float*)d_in[1];
    float* out = (float*)d_out;

    xcorr_stage1<<<NCH, 224>>>(data1, data2);
    xcorr_stage2<<<NCH, 128>>>(out);
}